// round 14
// baseline (speedup 1.0000x reference)
#include <cuda_runtime.h>
#include <cuda_bf16.h>
#include <cstdint>

#define DIN   128
#define DOUT  128
#define MAXN  100000
#define BN_EPS 1e-5f
#define NSM   148
#define DG_GRID (2 * NSM)               // persistent: 2 CTAs per SM, 1 wave

// Scratch (allocation-free rule: __device__ globals)
__device__ float g_y1[(size_t)MAXN * DIN];     // Y1 = feat @ W1  [N,128]
__device__ int   g_rowptr[MAXN + 1];
// [0..255]=colsum, [256..511]=colsumsq
__device__ float g_stats[512];

// ---------------------------------------------------------------------------
__device__ __forceinline__ void ffma2(unsigned long long& d,
                                      unsigned long long a,
                                      unsigned long long b) {
    asm("fma.rn.f32x2 %0, %1, %2, %3;" : "=l"(d) : "l"(a), "l"(b), "l"(d));
}
__device__ __forceinline__ unsigned long long pack2(float x) {
    unsigned long long r;
    unsigned int u = __float_as_uint(x);
    asm("mov.b64 %0, {%1, %1};" : "=l"(r) : "r"(u));
    return r;
}
__device__ __forceinline__ float f2lo(unsigned long long x) {
    return __uint_as_float((unsigned int)(x & 0xFFFFFFFFull));
}
__device__ __forceinline__ float f2hi(unsigned long long x) {
    return __uint_as_float((unsigned int)(x >> 32));
}
__device__ __forceinline__ uint32_t smem_u32(const void* p) {
    return (uint32_t)__cvta_generic_to_shared(p);
}
__device__ __forceinline__ void cp16(uint32_t dst, const void* src) {
    asm volatile("cp.async.cg.shared.global [%0], [%1], 16;"
                 :: "r"(dst), "l"(src));
}
#define CP_COMMIT() asm volatile("cp.async.commit_group;" ::: "memory")
#define CP_WAIT1()  asm volatile("cp.async.wait_group 1;" ::: "memory")
#define CP_WAIT0()  asm volatile("cp.async.wait_group 0;" ::: "memory")

// ---------------------------------------------------------------------------
__global__ void zero_stats_kernel() {
    g_stats[threadIdx.x] = 0.0f;          // 512 threads
}

// adj_rows is sorted; scatter row boundaries into CSR row_ptr.
__global__ void build_rowptr_kernel(const int* __restrict__ rows, int E, int N) {
    int e = blockIdx.x * blockDim.x + threadIdx.x;
    if (e >= E) return;
    int r = rows[e];
    int prev = (e == 0) ? -1 : rows[e - 1];
    for (int rr = prev + 1; rr <= r; rr++) g_rowptr[rr] = e;
    if (e == E - 1) {
        for (int rr = r + 1; rr <= N; rr++) g_rowptr[rr] = E;
    }
}

// ---------------------------------------------------------------------------
// Persistent double-GEMM: 296 CTAs (one full wave, 2/SM), each striding over
// M=64 x N=256 tiles -> no partial-wave tail (was ~21us of the R13 residual).
//   p0 = relu(feat@W0)+b0  -> out[:,0:128]  (+ BN column stats)
//   Y1 = feat@W1           -> g_y1          (raw; SpMM consumes it)
// cp.async double-buffered B tiles, register-staged A tile, row-paired FFMA2.
// SMEM 41.5KB/CTA: As[2][16][68] | Bs[2][16][256]; sred aliases tiles.
__global__ __launch_bounds__(256, 2)
void dgemm_kernel(const float* __restrict__ X,
                  const float* __restrict__ W0,
                  const float* __restrict__ W1,
                  const float* __restrict__ b0,
                  float* __restrict__ out,
                  int N, int ntiles) {
    __shared__ __align__(16) char smem_raw[2 * 16 * 68 * 4 + 2 * 16 * 256 * 4];
    float (*As)[16][68]  = (float (*)[16][68])smem_raw;
    float (*Bs)[16][256] = (float (*)[16][256])(smem_raw + 2 * 16 * 68 * 4);
    float (*sred_s)[128] = (float (*)[128])smem_raw;
    float (*sred_q)[128] = (float (*)[128])(smem_raw + 4096);

    int tid = threadIdx.x;
    int tx = tid & 31;                  // lane: 8 cols (4 W0-cols + 4 W1-cols)
    int ty = tid >> 5;                  // warp: 8 rows
    int arow = tid >> 2;                // A-load role: 0..63
    int akq  = (tid & 3) * 4;           // 0,4,8,12
    int bq   = tid & 63;                // B-load role
    int bkr  = tid >> 6;                // 0..3
    int bc4  = bq * 4;
    const float* bw = (bc4 < 128) ? W0 : W1;
    int bcc = (bc4 < 128) ? bc4 : bc4 - 128;
    float4 b0v = *(const float4*)&b0[tx * 4];

    for (int tile = blockIdx.x; tile < ntiles; tile += DG_GRID) {
        int m0  = tile * 64;
        int agr = m0 + arow;
        bool avalid = agr < N;
        const float* aptr = X + (size_t)agr * DIN + akq;

        unsigned long long acc2[4][8];
#pragma unroll
        for (int p = 0; p < 4; p++)
#pragma unroll
            for (int j = 0; j < 8; j++) acc2[p][j] = 0ull;

        // ---- prologue: A(0) direct; B(0), B(1) via cp.async ---------------
        {
            float4 a0 = make_float4(0.f, 0.f, 0.f, 0.f);
            if (avalid) a0 = *(const float4*)aptr;
            As[0][akq + 0][arow] = a0.x;
            As[0][akq + 1][arow] = a0.y;
            As[0][akq + 2][arow] = a0.z;
            As[0][akq + 3][arow] = a0.w;
        }
#pragma unroll
        for (int h = 0; h < 4; h++) {
            int k = bkr + h * 4;
            cp16(smem_u32(&Bs[0][k][bc4]), &bw[(size_t)k * DOUT + bcc]);
        }
        CP_COMMIT();
#pragma unroll
        for (int h = 0; h < 4; h++) {
            int k = bkr + h * 4;
            cp16(smem_u32(&Bs[1][k][bc4]), &bw[(size_t)(16 + k) * DOUT + bcc]);
        }
        CP_COMMIT();

        // ---- pipelined main loop (8 chunks of BK=16) ----------------------
#pragma unroll
        for (int i = 0; i < 8; i++) {
            int b = i & 1;
            if (i < 6) { CP_WAIT1(); } else { CP_WAIT0(); }
            __syncthreads();             // Bs[b] + As[b] ready for all

            float4 an = make_float4(0.f, 0.f, 0.f, 0.f);
            if (i + 1 < 8 && avalid)
                an = *(const float4*)(aptr + (i + 1) * 16);

#pragma unroll
            for (int kk = 0; kk < 16; kk++) {
                ulonglong2 a01 = *(const ulonglong2*)&As[b][kk][ty * 8];
                ulonglong2 a23 = *(const ulonglong2*)&As[b][kk][ty * 8 + 4];
                unsigned long long ap[4] = { a01.x, a01.y, a23.x, a23.y };
                float4 bA = *(const float4*)&Bs[b][kk][tx * 4];
                float4 bB = *(const float4*)&Bs[b][kk][128 + tx * 4];
                unsigned long long bd[8] = {
                    pack2(bA.x), pack2(bA.y), pack2(bA.z), pack2(bA.w),
                    pack2(bB.x), pack2(bB.y), pack2(bB.z), pack2(bB.w)
                };
#pragma unroll
                for (int p = 0; p < 4; p++)
#pragma unroll
                    for (int j = 0; j < 8; j++)
                        ffma2(acc2[p][j], ap[p], bd[j]);
            }

            if (i + 1 < 8) {
                As[b ^ 1][akq + 0][arow] = an.x;
                As[b ^ 1][akq + 1][arow] = an.y;
                As[b ^ 1][akq + 2][arow] = an.z;
                As[b ^ 1][akq + 3][arow] = an.w;
            }
            __syncthreads();             // all done reading Bs[b]/As tiles

            if (i + 2 < 8) {
#pragma unroll
                for (int h = 0; h < 4; h++) {
                    int k = bkr + h * 4;
                    cp16(smem_u32(&Bs[b][k][bc4]),
                         &bw[(size_t)((i + 2) * 16 + k) * DOUT + bcc]);
                }
                CP_COMMIT();
            }
        }

        // ---- epilogue (tiles dead; sred aliases them) ---------------------
        float psum[4] = {0.f, 0.f, 0.f, 0.f};
        float psq[4]  = {0.f, 0.f, 0.f, 0.f};

#pragma unroll
        for (int p = 0; p < 4; p++) {
#pragma unroll
            for (int half = 0; half < 2; half++) {
                int m = m0 + ty * 8 + 2 * p + half;
                if (m >= N) continue;
                float v0 = half ? f2hi(acc2[p][0]) : f2lo(acc2[p][0]);
                float v1 = half ? f2hi(acc2[p][1]) : f2lo(acc2[p][1]);
                float v2 = half ? f2hi(acc2[p][2]) : f2lo(acc2[p][2]);
                float v3 = half ? f2hi(acc2[p][3]) : f2lo(acc2[p][3]);
                float r0 = fmaxf(v0, 0.f) + b0v.x;
                float r1 = fmaxf(v1, 0.f) + b0v.y;
                float r2 = fmaxf(v2, 0.f) + b0v.z;
                float r3 = fmaxf(v3, 0.f) + b0v.w;
                *(float4*)&out[(size_t)m * (2 * DOUT) + tx * 4] =
                    make_float4(r0, r1, r2, r3);
                psum[0] += r0; psq[0] = fmaf(r0, r0, psq[0]);
                psum[1] += r1; psq[1] = fmaf(r1, r1, psq[1]);
                psum[2] += r2; psq[2] = fmaf(r2, r2, psq[2]);
                psum[3] += r3; psq[3] = fmaf(r3, r3, psq[3]);
                float y0 = half ? f2hi(acc2[p][4]) : f2lo(acc2[p][4]);
                float y1 = half ? f2hi(acc2[p][5]) : f2lo(acc2[p][5]);
                float y2 = half ? f2hi(acc2[p][6]) : f2lo(acc2[p][6]);
                float y3 = half ? f2hi(acc2[p][7]) : f2lo(acc2[p][7]);
                *(float4*)&g_y1[(size_t)m * DIN + tx * 4] =
                    make_float4(y0, y1, y2, y3);
            }
        }

        *(float4*)&sred_s[ty][tx * 4] =
            make_float4(psum[0], psum[1], psum[2], psum[3]);
        *(float4*)&sred_q[ty][tx * 4] =
            make_float4(psq[0], psq[1], psq[2], psq[3]);
        __syncthreads();
        if (tid < 128) {
            float s = 0.f, q = 0.f;
#pragma unroll
            for (int w = 0; w < 8; w++) {
                s += sred_s[w][tid];
                q += sred_q[w][tid];
            }
            atomicAdd(&g_stats[tid], s);
            atomicAdd(&g_stats[256 + tid], q);
        }
        __syncthreads();   // protect sred alias from next tile's A prologue
    }
}

// ---------------------------------------------------------------------------
// Fused SpMM: p1[n] = relu(sum_e val*Y1[col]) + b1 -> out[:,128:256],
// with p1 BN column stats fused in (smem reduction + global atomics).
// One warp per node, lane owns a float4. 4-edge unroll.
__global__ __launch_bounds__(256)
void spmm_fused_kernel(const float* __restrict__ vals,
                       const int*   __restrict__ cols,
                       const float* __restrict__ b1,
                       float* __restrict__ out,
                       int N) {
    __shared__ float s_sum[128], s_sq[128];
    int tid  = threadIdx.x;
    int warp = (blockIdx.x * blockDim.x + tid) >> 5;
    int lane = tid & 31;
    if (tid < 128) { s_sum[tid] = 0.f; s_sq[tid] = 0.f; }
    __syncthreads();

    if (warp < N) {
        int s = g_rowptr[warp];
        int e = g_rowptr[warp + 1];
        float4 acc0 = make_float4(0.f, 0.f, 0.f, 0.f);
        float4 acc1 = make_float4(0.f, 0.f, 0.f, 0.f);
        int t = s;
        for (; t + 3 < e; t += 4) {
            float v0 = __ldg(&vals[t]),     v1 = __ldg(&vals[t + 1]);
            float v2 = __ldg(&vals[t + 2]), v3 = __ldg(&vals[t + 3]);
            int c0 = __ldg(&cols[t]),     c1 = __ldg(&cols[t + 1]);
            int c2 = __ldg(&cols[t + 2]), c3 = __ldg(&cols[t + 3]);
            float4 x0 = __ldg(&((const float4*)&g_y1[(size_t)c0 * DIN])[lane]);
            float4 x1 = __ldg(&((const float4*)&g_y1[(size_t)c1 * DIN])[lane]);
            float4 x2 = __ldg(&((const float4*)&g_y1[(size_t)c2 * DIN])[lane]);
            float4 x3 = __ldg(&((const float4*)&g_y1[(size_t)c3 * DIN])[lane]);
            acc0.x = fmaf(v0, x0.x, acc0.x); acc0.y = fmaf(v0, x0.y, acc0.y);
            acc0.z = fmaf(v0, x0.z, acc0.z); acc0.w = fmaf(v0, x0.w, acc0.w);
            acc1.x = fmaf(v1, x1.x, acc1.x); acc1.y = fmaf(v1, x1.y, acc1.y);
            acc1.z = fmaf(v1, x1.z, acc1.z); acc1.w = fmaf(v1, x1.w, acc1.w);
            acc0.x = fmaf(v2, x2.x, acc0.x); acc0.y = fmaf(v2, x2.y, acc0.y);
            acc0.z = fmaf(v2, x2.z, acc0.z); acc0.w = fmaf(v2, x2.w, acc0.w);
            acc1.x = fmaf(v3, x3.x, acc1.x); acc1.y = fmaf(v3, x3.y, acc1.y);
            acc1.z = fmaf(v3, x3.z, acc1.z); acc1.w = fmaf(v3, x3.w, acc1.w);
        }
        for (; t < e; t++) {
            float v0 = __ldg(&vals[t]);
            int   c0 = __ldg(&cols[t]);
            float4 x0 = __ldg(&((const float4*)&g_y1[(size_t)c0 * DIN])[lane]);
            acc0.x = fmaf(v0, x0.x, acc0.x); acc0.y = fmaf(v0, x0.y, acc0.y);
            acc0.z = fmaf(v0, x0.z, acc0.z); acc0.w = fmaf(v0, x0.w, acc0.w);
        }
        float4 bb = __ldg(&((const float4*)b1)[lane]);
        float4 r;
        r.x = fmaxf(acc0.x + acc1.x, 0.f) + bb.x;
        r.y = fmaxf(acc0.y + acc1.y, 0.f) + bb.y;
        r.z = fmaxf(acc0.z + acc1.z, 0.f) + bb.z;
        r.w = fmaxf(acc0.w + acc1.w, 0.f) + bb.w;
        *(float4*)&out[(size_t)warp * (2 * DOUT) + DOUT + lane * 4] = r;
        atomicAdd(&s_sum[lane * 4 + 0], r.x);
        atomicAdd(&s_sum[lane * 4 + 1], r.y);
        atomicAdd(&s_sum[lane * 4 + 2], r.z);
        atomicAdd(&s_sum[lane * 4 + 3], r.w);
        atomicAdd(&s_sq[lane * 4 + 0], r.x * r.x);
        atomicAdd(&s_sq[lane * 4 + 1], r.y * r.y);
        atomicAdd(&s_sq[lane * 4 + 2], r.z * r.z);
        atomicAdd(&s_sq[lane * 4 + 3], r.w * r.w);
    }
    __syncthreads();
    if (tid < 128) {
        atomicAdd(&g_stats[128 + tid], s_sum[tid]);
        atomicAdd(&g_stats[384 + tid], s_sq[tid]);
    }
}

// ---------------------------------------------------------------------------
// Normalize one 128-col half of out; BN finalize inlined in the prologue.
// half=0 -> cols 0..127, half=1 -> cols 128..255.
__global__ __launch_bounds__(256)
void bn_apply_half_kernel(float* __restrict__ out,
                          const float* __restrict__ gamma,
                          const float* __restrict__ beta,
                          int N, int half) {
    __shared__ float scale[128], shift[128];
    int tid = threadIdx.x;
    if (tid < 128) {
        int c = half * 128 + tid;
        float inv_n = 1.0f / (float)N;
        float mean = g_stats[c] * inv_n;
        float var  = g_stats[256 + c] * inv_n - mean * mean;
        float s = __ldg(&gamma[c]) * rsqrtf(var + BN_EPS);
        scale[tid] = s;
        shift[tid] = __ldg(&beta[c]) - mean * s;
    }
    __syncthreads();

    size_t total = (size_t)N * 32;          // float4s in this half
    size_t i = (size_t)blockIdx.x * blockDim.x + tid;
    size_t stride = (size_t)gridDim.x * blockDim.x;
    const float4* scale4 = (const float4*)scale;
    const float4* shift4 = (const float4*)shift;
    for (; i < total; i += stride) {
        size_t row = i >> 5;
        int    q   = (int)(i & 31);
        float4 s  = scale4[q];
        float4 sh = shift4[q];
        size_t idx = row * 64 + half * 32 + q;
        float4 v = ((float4*)out)[idx];
        v.x = fmaf(v.x, s.x, sh.x);
        v.y = fmaf(v.y, s.y, sh.y);
        v.z = fmaf(v.z, s.z, sh.z);
        v.w = fmaf(v.w, s.w, sh.w);
        ((float4*)out)[idx] = v;
    }
}

// ---------------------------------------------------------------------------
extern "C" void kernel_launch(void* const* d_in, const int* in_sizes, int n_in,
                              void* d_out, int out_size) {
    const float* feat     = (const float*)d_in[0];
    const float* adj_vals = (const float*)d_in[1];
    const float* W0       = (const float*)d_in[2];
    const float* W1       = (const float*)d_in[3];
    const float* b0       = (const float*)d_in[4];
    const float* b1       = (const float*)d_in[5];
    const float* gamma    = (const float*)d_in[6];
    const float* beta     = (const float*)d_in[7];
    const int*   adj_rows = (const int*)d_in[8];
    const int*   adj_cols = (const int*)d_in[9];
    float* out = (float*)d_out;

    int N = in_sizes[0] / DIN;
    int E = in_sizes[1];

    // Side stream + events, created once on the eager correctness call
    // (before graph capture), reused inside capture via event fork/join.
    static cudaStream_t s1 = nullptr;
    static cudaEvent_t  eZ = nullptr, eR = nullptr, eD = nullptr, eA0 = nullptr;
    if (s1 == nullptr) {
        cudaStreamCreateWithFlags(&s1, cudaStreamNonBlocking);
        cudaEventCreateWithFlags(&eZ,  cudaEventDisableTiming);
        cudaEventCreateWithFlags(&eR,  cudaEventDisableTiming);
        cudaEventCreateWithFlags(&eD,  cudaEventDisableTiming);
        cudaEventCreateWithFlags(&eA0, cudaEventDisableTiming);
    }

    int ntiles  = (N + 63) / 64;
    int sblocks = (N * 32 + 255) / 256;
    int ablocks = (N * 32 + 255) / 256;
    if (ablocks > 8192) ablocks = 8192;
    int gblocks = (ntiles < DG_GRID) ? ntiles : DG_GRID;

    // main: zero stats, then FORK
    zero_stats_kernel<<<1, 512>>>();
    cudaEventRecord(eZ, 0);

    // side (forked): rowptr overlaps dgemm
    cudaStreamWaitEvent(s1, eZ, 0);
    build_rowptr_kernel<<<(E + 255) / 256, 256, 0, s1>>>(adj_rows, E, N);
    cudaEventRecord(eR, s1);

    // main: persistent dgemm (one full wave)
    dgemm_kernel<<<gblocks, 256>>>(feat, W0, W1, b0, out, N, ntiles);
    cudaEventRecord(eD, 0);

    // side: p0's BN half (finalize inlined) runs during spmm
    cudaStreamWaitEvent(s1, eD, 0);
    bn_apply_half_kernel<<<ablocks, 256, 0, s1>>>(out, gamma, beta, N, 0);
    cudaEventRecord(eA0, s1);

    // main: spmm (needs rowptr + Y1; stats fused) -> p1 BN half
    cudaStreamWaitEvent(0, eR, 0);
    spmm_fused_kernel<<<sblocks, 256>>>(adj_vals, adj_cols, b1, out, N);
    bn_apply_half_kernel<<<ablocks, 256>>>(out, gamma, beta, N, 1);

    // join side branch before capture ends
    cudaStreamWaitEvent(0, eA0, 0);
}

// round 15
// speedup vs baseline: 1.0998x; 1.0998x over previous
#include <cuda_runtime.h>
#include <cuda_bf16.h>
#include <cstdint>

#define DIN   128
#define DOUT  128
#define MAXN  100000
#define BN_EPS 1e-5f

// dgemm tile: M=64 x N=256, BK=32, double-buffered dynamic SMEM
#define DG_AS_BYTES (2 * 32 * 68 * 4)        // 17408
#define DG_BS_BYTES (2 * 32 * 256 * 4)       // 65536
#define DG_SMEM     (DG_AS_BYTES + DG_BS_BYTES)

// Scratch (allocation-free rule: __device__ globals)
__device__ float g_y1[(size_t)MAXN * DIN];     // Y1 = feat @ W1  [N,128]
__device__ int   g_rowptr[MAXN + 1];
// [0..255]=colsum, [256..511]=colsumsq
__device__ float g_stats[512];

// ---------------------------------------------------------------------------
__device__ __forceinline__ void ffma2(unsigned long long& d,
                                      unsigned long long a,
                                      unsigned long long b) {
    asm("fma.rn.f32x2 %0, %1, %2, %3;" : "=l"(d) : "l"(a), "l"(b), "l"(d));
}
__device__ __forceinline__ unsigned long long pack2(float x) {
    unsigned long long r;
    unsigned int u = __float_as_uint(x);
    asm("mov.b64 %0, {%1, %1};" : "=l"(r) : "r"(u));
    return r;
}
__device__ __forceinline__ float f2lo(unsigned long long x) {
    return __uint_as_float((unsigned int)(x & 0xFFFFFFFFull));
}
__device__ __forceinline__ float f2hi(unsigned long long x) {
    return __uint_as_float((unsigned int)(x >> 32));
}
__device__ __forceinline__ uint32_t smem_u32(const void* p) {
    return (uint32_t)__cvta_generic_to_shared(p);
}
__device__ __forceinline__ void cp16(uint32_t dst, const void* src) {
    asm volatile("cp.async.cg.shared.global [%0], [%1], 16;"
                 :: "r"(dst), "l"(src));
}
#define CP_COMMIT() asm volatile("cp.async.commit_group;" ::: "memory")
#define CP_WAIT1()  asm volatile("cp.async.wait_group 1;" ::: "memory")
#define CP_WAIT0()  asm volatile("cp.async.wait_group 0;" ::: "memory")

// ---------------------------------------------------------------------------
__global__ void zero_stats_kernel() {
    g_stats[threadIdx.x] = 0.0f;          // 512 threads
}

// adj_rows is sorted; scatter row boundaries into CSR row_ptr.
__global__ void build_rowptr_kernel(const int* __restrict__ rows, int E, int N) {
    int e = blockIdx.x * blockDim.x + threadIdx.x;
    if (e >= E) return;
    int r = rows[e];
    int prev = (e == 0) ? -1 : rows[e - 1];
    for (int rr = prev + 1; rr <= r; rr++) g_rowptr[rr] = e;
    if (e == E - 1) {
        for (int rr = r + 1; rr <= N; rr++) g_rowptr[rr] = E;
    }
}

// ---------------------------------------------------------------------------
// Double-GEMM, M=64 x N=256 tile, BK=32 (4 chunks -> 8 barriers vs 16),
// 256 threads, 2 CTAs/SM, cp.async double-buffered B, reg-staged A.
//   p0 = relu(feat@W0)+b0  -> out[:,0:128]  (+ BN column stats)
//   Y1 = feat@W1           -> g_y1          (raw; SpMM consumes it)
// ROW-paired FFMA2 accumulators (a-pairs free from As float4 LDS).
// Dynamic SMEM 82.9KB/CTA: As[2][32][68] | Bs[2][32][256]; sred aliases tiles.
__global__ __launch_bounds__(256, 2)
void dgemm_kernel(const float* __restrict__ X,
                  const float* __restrict__ W0,
                  const float* __restrict__ W1,
                  const float* __restrict__ b0,
                  float* __restrict__ out,
                  int N) {
    extern __shared__ __align__(16) char smem_raw[];
    float (*As)[32][68]  = (float (*)[32][68])smem_raw;
    float (*Bs)[32][256] = (float (*)[32][256])(smem_raw + DG_AS_BYTES);
    float (*sred_s)[128] = (float (*)[128])smem_raw;
    float (*sred_q)[128] = (float (*)[128])(smem_raw + 4096);

    int tid = threadIdx.x;
    int tx = tid & 31;                  // lane: 8 cols (4 W0-cols + 4 W1-cols)
    int ty = tid >> 5;                  // warp: 8 rows
    int m0 = blockIdx.x * 64;

    // A-load role: two float4 (k akq.. and akq+16..) per chunk, transposed
    int arow = tid >> 2;                // 0..63
    int akq  = (tid & 3) * 4;           // 0,4,8,12
    int agr  = m0 + arow;
    bool avalid = agr < N;
    const float* aptr = X + (size_t)agr * DIN + akq;   // +32*i per chunk

    // B-load role: 8 x 16B per chunk (k = bkr + 4h, h=0..7)
    int bq  = tid & 63;
    int bkr = tid >> 6;                 // 0..3
    int bc4 = bq * 4;
    const float* bw = (bc4 < 128) ? W0 : W1;
    int bcc = (bc4 < 128) ? bc4 : bc4 - 128;

    // acc2[p][j]: row-pair p (rows ty*8+2p, +1), j: 0..3 W0 cols, 4..7 W1 cols
    unsigned long long acc2[4][8];
#pragma unroll
    for (int p = 0; p < 4; p++)
#pragma unroll
        for (int j = 0; j < 8; j++) acc2[p][j] = 0ull;

    // ---- prologue: A(0) direct; B(0), B(1) via cp.async -------------------
    {
        float4 a0 = make_float4(0.f, 0.f, 0.f, 0.f);
        float4 a1 = make_float4(0.f, 0.f, 0.f, 0.f);
        if (avalid) { a0 = *(const float4*)aptr;
                      a1 = *(const float4*)(aptr + 16); }
        As[0][akq + 0][arow] = a0.x;  As[0][akq + 1][arow] = a0.y;
        As[0][akq + 2][arow] = a0.z;  As[0][akq + 3][arow] = a0.w;
        As[0][akq + 16][arow] = a1.x; As[0][akq + 17][arow] = a1.y;
        As[0][akq + 18][arow] = a1.z; As[0][akq + 19][arow] = a1.w;
    }
#pragma unroll
    for (int h = 0; h < 8; h++) {
        int k = bkr + h * 4;
        cp16(smem_u32(&Bs[0][k][bc4]), &bw[(size_t)k * DOUT + bcc]);
    }
    CP_COMMIT();
#pragma unroll
    for (int h = 0; h < 8; h++) {
        int k = bkr + h * 4;
        cp16(smem_u32(&Bs[1][k][bc4]), &bw[(size_t)(32 + k) * DOUT + bcc]);
    }
    CP_COMMIT();

    // ---- pipelined main loop (4 chunks of BK=32) --------------------------
#pragma unroll
    for (int i = 0; i < 4; i++) {
        int b = i & 1;
        if (i < 3) { CP_WAIT1(); } else { CP_WAIT0(); }
        __syncthreads();                 // Bs[b] + As[b] ready for all

        // prefetch A(i+1) into regs (latency hidden behind compute)
        float4 an0 = make_float4(0.f, 0.f, 0.f, 0.f);
        float4 an1 = make_float4(0.f, 0.f, 0.f, 0.f);
        if (i + 1 < 4 && avalid) {
            an0 = *(const float4*)(aptr + (i + 1) * 32);
            an1 = *(const float4*)(aptr + (i + 1) * 32 + 16);
        }

#pragma unroll
        for (int kk = 0; kk < 32; kk++) {
            ulonglong2 a01 = *(const ulonglong2*)&As[b][kk][ty * 8];
            ulonglong2 a23 = *(const ulonglong2*)&As[b][kk][ty * 8 + 4];
            unsigned long long ap[4] = { a01.x, a01.y, a23.x, a23.y };
            float4 bA = *(const float4*)&Bs[b][kk][tx * 4];
            float4 bB = *(const float4*)&Bs[b][kk][128 + tx * 4];
            unsigned long long bd[8] = {
                pack2(bA.x), pack2(bA.y), pack2(bA.z), pack2(bA.w),
                pack2(bB.x), pack2(bB.y), pack2(bB.z), pack2(bB.w)
            };
#pragma unroll
            for (int p = 0; p < 4; p++)
#pragma unroll
                for (int j = 0; j < 8; j++)
                    ffma2(acc2[p][j], ap[p], bd[j]);
        }

        // store A(i+1) into the other buffer (safe: all warps past this
        // iter's first barrier => compute(i-1) on that buffer is done)
        if (i + 1 < 4) {
            As[b ^ 1][akq + 0][arow] = an0.x;  As[b ^ 1][akq + 1][arow] = an0.y;
            As[b ^ 1][akq + 2][arow] = an0.z;  As[b ^ 1][akq + 3][arow] = an0.w;
            As[b ^ 1][akq + 16][arow] = an1.x; As[b ^ 1][akq + 17][arow] = an1.y;
            As[b ^ 1][akq + 18][arow] = an1.z; As[b ^ 1][akq + 19][arow] = an1.w;
        }
        __syncthreads();                 // all done reading Bs[b]/As tiles

        if (i + 2 < 4) {
#pragma unroll
            for (int h = 0; h < 8; h++) {
                int k = bkr + h * 4;
                cp16(smem_u32(&Bs[b][k][bc4]),
                     &bw[(size_t)((i + 2) * 32 + k) * DOUT + bcc]);
            }
            CP_COMMIT();
        }
    }

    // Epilogue (tiles dead; sred aliases them)
    float4 b0v = *(const float4*)&b0[tx * 4];
    float psum[4] = {0.f, 0.f, 0.f, 0.f};
    float psq[4]  = {0.f, 0.f, 0.f, 0.f};

#pragma unroll
    for (int p = 0; p < 4; p++) {
#pragma unroll
        for (int half = 0; half < 2; half++) {
            int m = m0 + ty * 8 + 2 * p + half;
            if (m >= N) continue;
            float v0 = half ? f2hi(acc2[p][0]) : f2lo(acc2[p][0]);
            float v1 = half ? f2hi(acc2[p][1]) : f2lo(acc2[p][1]);
            float v2 = half ? f2hi(acc2[p][2]) : f2lo(acc2[p][2]);
            float v3 = half ? f2hi(acc2[p][3]) : f2lo(acc2[p][3]);
            float r0 = fmaxf(v0, 0.f) + b0v.x;
            float r1 = fmaxf(v1, 0.f) + b0v.y;
            float r2 = fmaxf(v2, 0.f) + b0v.z;
            float r3 = fmaxf(v3, 0.f) + b0v.w;
            *(float4*)&out[(size_t)m * (2 * DOUT) + tx * 4] =
                make_float4(r0, r1, r2, r3);
            psum[0] += r0; psq[0] = fmaf(r0, r0, psq[0]);
            psum[1] += r1; psq[1] = fmaf(r1, r1, psq[1]);
            psum[2] += r2; psq[2] = fmaf(r2, r2, psq[2]);
            psum[3] += r3; psq[3] = fmaf(r3, r3, psq[3]);
            float y0 = half ? f2hi(acc2[p][4]) : f2lo(acc2[p][4]);
            float y1 = half ? f2hi(acc2[p][5]) : f2lo(acc2[p][5]);
            float y2 = half ? f2hi(acc2[p][6]) : f2lo(acc2[p][6]);
            float y3 = half ? f2hi(acc2[p][7]) : f2lo(acc2[p][7]);
            *(float4*)&g_y1[(size_t)m * DIN + tx * 4] =
                make_float4(y0, y1, y2, y3);
        }
    }

    // Stats: conflict-free shared staging, then one atomic pass
    *(float4*)&sred_s[ty][tx * 4] = make_float4(psum[0], psum[1], psum[2], psum[3]);
    *(float4*)&sred_q[ty][tx * 4] = make_float4(psq[0], psq[1], psq[2], psq[3]);
    __syncthreads();
    if (tid < 128) {
        float s = 0.f, q = 0.f;
#pragma unroll
        for (int w = 0; w < 8; w++) { s += sred_s[w][tid]; q += sred_q[w][tid]; }
        atomicAdd(&g_stats[tid], s);
        atomicAdd(&g_stats[256 + tid], q);
    }
}

// ---------------------------------------------------------------------------
// Fused SpMM: p1[n] = relu(sum_e val*Y1[col]) + b1 -> out[:,128:256],
// with p1 BN column stats fused in (smem reduction + global atomics).
// One warp per node, lane owns a float4. 4-edge unroll.
__global__ __launch_bounds__(256)
void spmm_fused_kernel(const float* __restrict__ vals,
                       const int*   __restrict__ cols,
                       const float* __restrict__ b1,
                       float* __restrict__ out,
                       int N) {
    __shared__ float s_sum[128], s_sq[128];
    int tid  = threadIdx.x;
    int warp = (blockIdx.x * blockDim.x + tid) >> 5;
    int lane = tid & 31;
    if (tid < 128) { s_sum[tid] = 0.f; s_sq[tid] = 0.f; }
    __syncthreads();

    if (warp < N) {
        int s = g_rowptr[warp];
        int e = g_rowptr[warp + 1];
        float4 acc0 = make_float4(0.f, 0.f, 0.f, 0.f);
        float4 acc1 = make_float4(0.f, 0.f, 0.f, 0.f);
        int t = s;
        for (; t + 3 < e; t += 4) {
            float v0 = __ldg(&vals[t]),     v1 = __ldg(&vals[t + 1]);
            float v2 = __ldg(&vals[t + 2]), v3 = __ldg(&vals[t + 3]);
            int c0 = __ldg(&cols[t]),     c1 = __ldg(&cols[t + 1]);
            int c2 = __ldg(&cols[t + 2]), c3 = __ldg(&cols[t + 3]);
            float4 x0 = __ldg(&((const float4*)&g_y1[(size_t)c0 * DIN])[lane]);
            float4 x1 = __ldg(&((const float4*)&g_y1[(size_t)c1 * DIN])[lane]);
            float4 x2 = __ldg(&((const float4*)&g_y1[(size_t)c2 * DIN])[lane]);
            float4 x3 = __ldg(&((const float4*)&g_y1[(size_t)c3 * DIN])[lane]);
            acc0.x = fmaf(v0, x0.x, acc0.x); acc0.y = fmaf(v0, x0.y, acc0.y);
            acc0.z = fmaf(v0, x0.z, acc0.z); acc0.w = fmaf(v0, x0.w, acc0.w);
            acc1.x = fmaf(v1, x1.x, acc1.x); acc1.y = fmaf(v1, x1.y, acc1.y);
            acc1.z = fmaf(v1, x1.z, acc1.z); acc1.w = fmaf(v1, x1.w, acc1.w);
            acc0.x = fmaf(v2, x2.x, acc0.x); acc0.y = fmaf(v2, x2.y, acc0.y);
            acc0.z = fmaf(v2, x2.z, acc0.z); acc0.w = fmaf(v2, x2.w, acc0.w);
            acc1.x = fmaf(v3, x3.x, acc1.x); acc1.y = fmaf(v3, x3.y, acc1.y);
            acc1.z = fmaf(v3, x3.z, acc1.z); acc1.w = fmaf(v3, x3.w, acc1.w);
        }
        for (; t < e; t++) {
            float v0 = __ldg(&vals[t]);
            int   c0 = __ldg(&cols[t]);
            float4 x0 = __ldg(&((const float4*)&g_y1[(size_t)c0 * DIN])[lane]);
            acc0.x = fmaf(v0, x0.x, acc0.x); acc0.y = fmaf(v0, x0.y, acc0.y);
            acc0.z = fmaf(v0, x0.z, acc0.z); acc0.w = fmaf(v0, x0.w, acc0.w);
        }
        float4 bb = __ldg(&((const float4*)b1)[lane]);
        float4 r;
        r.x = fmaxf(acc0.x + acc1.x, 0.f) + bb.x;
        r.y = fmaxf(acc0.y + acc1.y, 0.f) + bb.y;
        r.z = fmaxf(acc0.z + acc1.z, 0.f) + bb.z;
        r.w = fmaxf(acc0.w + acc1.w, 0.f) + bb.w;
        *(float4*)&out[(size_t)warp * (2 * DOUT) + DOUT + lane * 4] = r;
        atomicAdd(&s_sum[lane * 4 + 0], r.x);
        atomicAdd(&s_sum[lane * 4 + 1], r.y);
        atomicAdd(&s_sum[lane * 4 + 2], r.z);
        atomicAdd(&s_sum[lane * 4 + 3], r.w);
        atomicAdd(&s_sq[lane * 4 + 0], r.x * r.x);
        atomicAdd(&s_sq[lane * 4 + 1], r.y * r.y);
        atomicAdd(&s_sq[lane * 4 + 2], r.z * r.z);
        atomicAdd(&s_sq[lane * 4 + 3], r.w * r.w);
    }
    __syncthreads();
    if (tid < 128) {
        atomicAdd(&g_stats[128 + tid], s_sum[tid]);
        atomicAdd(&g_stats[384 + tid], s_sq[tid]);
    }
}

// ---------------------------------------------------------------------------
// Normalize one 128-col half of out; BN finalize inlined in the prologue.
// half=0 -> cols 0..127, half=1 -> cols 128..255.
__global__ __launch_bounds__(256)
void bn_apply_half_kernel(float* __restrict__ out,
                          const float* __restrict__ gamma,
                          const float* __restrict__ beta,
                          int N, int half) {
    __shared__ float scale[128], shift[128];
    int tid = threadIdx.x;
    if (tid < 128) {
        int c = half * 128 + tid;
        float inv_n = 1.0f / (float)N;
        float mean = g_stats[c] * inv_n;
        float var  = g_stats[256 + c] * inv_n - mean * mean;
        float s = __ldg(&gamma[c]) * rsqrtf(var + BN_EPS);
        scale[tid] = s;
        shift[tid] = __ldg(&beta[c]) - mean * s;
    }
    __syncthreads();

    size_t total = (size_t)N * 32;          // float4s in this half
    size_t i = (size_t)blockIdx.x * blockDim.x + tid;
    size_t stride = (size_t)gridDim.x * blockDim.x;
    const float4* scale4 = (const float4*)scale;
    const float4* shift4 = (const float4*)shift;
    for (; i < total; i += stride) {
        size_t row = i >> 5;
        int    q   = (int)(i & 31);
        float4 s  = scale4[q];
        float4 sh = shift4[q];
        size_t idx = row * 64 + half * 32 + q;
        float4 v = ((float4*)out)[idx];
        v.x = fmaf(v.x, s.x, sh.x);
        v.y = fmaf(v.y, s.y, sh.y);
        v.z = fmaf(v.z, s.z, sh.z);
        v.w = fmaf(v.w, s.w, sh.w);
        ((float4*)out)[idx] = v;
    }
}

// ---------------------------------------------------------------------------
extern "C" void kernel_launch(void* const* d_in, const int* in_sizes, int n_in,
                              void* d_out, int out_size) {
    const float* feat     = (const float*)d_in[0];
    const float* adj_vals = (const float*)d_in[1];
    const float* W0       = (const float*)d_in[2];
    const float* W1       = (const float*)d_in[3];
    const float* b0       = (const float*)d_in[4];
    const float* b1       = (const float*)d_in[5];
    const float* gamma    = (const float*)d_in[6];
    const float* beta     = (const float*)d_in[7];
    const int*   adj_rows = (const int*)d_in[8];
    const int*   adj_cols = (const int*)d_in[9];
    float* out = (float*)d_out;

    int N = in_sizes[0] / DIN;
    int E = in_sizes[1];

    // Side stream + events, created once on the eager correctness call
    // (before graph capture), reused inside capture via event fork/join.
    // Dynamic-SMEM attribute also set once here (not a stream op).
    static cudaStream_t s1 = nullptr;
    static cudaEvent_t  eZ = nullptr, eR = nullptr, eD = nullptr, eA0 = nullptr;
    if (s1 == nullptr) {
        cudaStreamCreateWithFlags(&s1, cudaStreamNonBlocking);
        cudaEventCreateWithFlags(&eZ,  cudaEventDisableTiming);
        cudaEventCreateWithFlags(&eR,  cudaEventDisableTiming);
        cudaEventCreateWithFlags(&eD,  cudaEventDisableTiming);
        cudaEventCreateWithFlags(&eA0, cudaEventDisableTiming);
        cudaFuncSetAttribute(dgemm_kernel,
                             cudaFuncAttributeMaxDynamicSharedMemorySize,
                             DG_SMEM);
    }

    int gblocks = (N + 63) / 64;
    int sblocks = (N * 32 + 255) / 256;
    int ablocks = (N * 32 + 255) / 256;
    if (ablocks > 8192) ablocks = 8192;

    // main: zero stats, then FORK
    zero_stats_kernel<<<1, 512>>>();
    cudaEventRecord(eZ, 0);

    // side (forked): rowptr overlaps dgemm
    cudaStreamWaitEvent(s1, eZ, 0);
    build_rowptr_kernel<<<(E + 255) / 256, 256, 0, s1>>>(adj_rows, E, N);
    cudaEventRecord(eR, s1);

    // main: dgemm (BK=32, dynamic smem)
    dgemm_kernel<<<gblocks, 256, DG_SMEM>>>(feat, W0, W1, b0, out, N);
    cudaEventRecord(eD, 0);

    // side: p0's BN half (finalize inlined) runs during spmm
    cudaStreamWaitEvent(s1, eD, 0);
    bn_apply_half_kernel<<<ablocks, 256, 0, s1>>>(out, gamma, beta, N, 0);
    cudaEventRecord(eA0, s1);

    // main: spmm (needs rowptr + Y1; stats fused) -> p1 BN half
    cudaStreamWaitEvent(0, eR, 0);
    spmm_fused_kernel<<<sblocks, 256>>>(adj_vals, adj_cols, b1, out, N);
    bn_apply_half_kernel<<<ablocks, 256>>>(out, gamma, beta, N, 1);

    // join side branch before capture ends
    cudaStreamWaitEvent(0, eA0, 0);
}